// round 6
// baseline (speedup 1.0000x reference)
#include <cuda_runtime.h>
#include <math.h>
#include <stdint.h>

#define Dd 128
#define Hh 512
#define Ww 512
#define OD 32
#define HW (Hh*Ww)
#define HW4 (HW/4)
#define INV_SQRT_2PI 0.3989422804014327f

// scratch: z-conv output (32,512,512) f32 = 33.5 MB
__device__ __align__(16) float g_tmp1[(size_t)OD * HW];
__device__ unsigned g_minb;
__device__ unsigned g_maxb;

__device__ __forceinline__ unsigned f2o(float f) {
    unsigned u = __float_as_uint(f);
    return (u & 0x80000000u) ? ~u : (u | 0x80000000u);
}
__device__ __forceinline__ float o2f(unsigned u) {
    return (u & 0x80000000u) ? __uint_as_float(u ^ 0x80000000u)
                             : __uint_as_float(~u);
}

// ---------------------------------------------------------------------------
// Kernel 1: strided z-conv CHUNK (8 output planes), rolling accumulators,
// 8-stage cp.async ring with L2::evict_first on the read-once input stream
// (keeps the scratch L2-resident for k_xyconv).  No __syncthreads.
// out[zo] = sum_{kz=0..8} wz[kz] * in[4*zo - 3 + kz]
// ---------------------------------------------------------------------------
__global__ void __launch_bounds__(128) k_zconv(
    const float4* __restrict__ in,
    const float* __restrict__ p_mu, const float* __restrict__ p_sig,
    const float* __restrict__ p_bz, int zo0)
{
    __shared__ float4 sb[8][128];

    int t = threadIdx.x;
    if (zo0 == 0 && blockIdx.x == 0 && t == 0) {
        g_minb = 0xFFFFFFFFu;
        g_maxb = 0u;
    }

    int idx = blockIdx.x * 128 + t;             // 0 .. HW4-1
    int zstart = 4 * zo0 - 3;                   // input z at iz=0 (37 planes)
    const float4* p0 = in + idx;
    unsigned sbase = (unsigned)__cvta_generic_to_shared(&sb[0][0]);

    uint64_t pol;
    asm("createpolicy.fractional.L2::evict_first.b64 %0, 1.0;" : "=l"(pol));

    float bz  = *p_bz;
    float z0  = expf(*p_mu + 0.5f * (*p_sig) * (*p_sig));
    float amp = INV_SQRT_2PI * z0;
    float inv2b2 = 1.0f / (2.0f * bz * bz);

    float wz[9];
#pragma unroll
    for (int k = 0; k < 9; k++) {
        float d = (float)(k - 4);
        wz[k] = expf(-d * d * inv2b2) * amp;
    }

    float4 acc[3];
#pragma unroll
    for (int j = 0; j < 3; j++) acc[j] = make_float4(0.f, 0.f, 0.f, 0.f);

#define ISSUE(P) do {                                                         \
        int z_ = zstart + (P);                                                \
        int ok_ = ((unsigned)z_ < 128u) ? 16 : 0;                             \
        int zc_ = z_ < 0 ? 0 : (z_ > 127 ? 127 : z_);                         \
        unsigned sa_ = sbase + ((((P) & 7) * 128 + t) * 16u);                 \
        asm volatile(                                                         \
            "cp.async.cg.shared.global.L2::cache_hint [%0], [%1], 16, %2, %3;"\
            :: "r"(sa_), "l"(p0 + (size_t)zc_ * HW4), "r"(ok_), "l"(pol)      \
            : "memory");                                                      \
        asm volatile("cp.async.commit_group;" ::: "memory");                  \
    } while (0)
#define WG(n) asm volatile("cp.async.wait_group " #n ";" ::: "memory")

    // prologue: planes 0..6 in flight
    ISSUE(0); ISSUE(1); ISSUE(2); ISSUE(3); ISSUE(4); ISSUE(5); ISSUE(6);

    float4* outp = reinterpret_cast<float4*>(g_tmp1) + idx;

#pragma unroll
    for (int iz = 0; iz < 37; iz++) {
        if (iz + 7 < 37)      { ISSUE(iz + 7); WG(7); }
        else if (iz == 30)    WG(6);
        else if (iz == 31)    WG(5);
        else if (iz == 32)    WG(4);
        else if (iz == 33)    WG(3);
        else if (iz == 34)    WG(2);
        else if (iz == 35)    WG(1);
        else                  WG(0);

        float4 v = sb[iz & 7][t];
        int c = iz >> 2, q = iz & 3;            // compile-time (full unroll)

        if (q == 0 && c >= 2) {                 // kz=8 tap, retire j=c-2
            int j = c - 2;                      // 0..7
            int s = j % 3;
            float w = wz[8];
            acc[s].x += w * v.x; acc[s].y += w * v.y;
            acc[s].z += w * v.z; acc[s].w += w * v.w;
            outp[(size_t)(zo0 + j) * HW4] = acc[s];
            acc[s] = make_float4(0.f, 0.f, 0.f, 0.f);
        }
        if (c >= 1 && c <= 8) {                 // kz=4+q tap for j=c-1
            int s = (c - 1) % 3;
            float w = wz[4 + q];
            acc[s].x += w * v.x; acc[s].y += w * v.y;
            acc[s].z += w * v.z; acc[s].w += w * v.w;
        }
        if (c <= 7) {                           // kz=q tap for j=c
            int s = c % 3;
            float w = wz[q];
            acc[s].x += w * v.x; acc[s].y += w * v.y;
            acc[s].z += w * v.z; acc[s].w += w * v.w;
        }
    }
#undef ISSUE
#undef WG
}

// ---------------------------------------------------------------------------
// Kernel 2: fused x-conv + y-conv CHUNK (8 planes), 64x64 tile (72x72 halo),
// single in-place smem buffer, padded stride 73, register sliding windows,
// fused global min/max.  288 threads.
// ---------------------------------------------------------------------------
#define SIN 73
__global__ void __launch_bounds__(288) k_xyconv(
    const float* __restrict__ p_bxy, float* __restrict__ out, int zbase)
{
    __shared__ float s_in[72 * SIN];
    __shared__ float smin[16], smax[16];

    int z  = zbase + blockIdx.z;
    int X0 = blockIdx.y * 64;
    int Y0 = blockIdx.x * 64;
    int t  = threadIdx.x;

    float bxy = *p_bxy;
    float inv2b2 = 1.0f / (2.0f * bxy * bxy);
    float w[9];
#pragma unroll
    for (int k = 0; k < 9; k++) {
        float d = (float)(k - 4);
        w[k] = expf(-d * d * inv2b2);
    }

    const float* src = g_tmp1 + (size_t)z * HW;

    // ---- Phase A: load 72x72 halo (zero padded), coalesced ----
#pragma unroll
    for (int it = 0; it < 18; it++) {            // 72*72 / 288 = 18
        int i = it * 288 + t;
        int r = i / 72, c = i % 72;
        int gx = X0 - 4 + r, gy = Y0 - 4 + c;
        s_in[r * SIN + c] = (gx >= 0 && gx < Hh && gy >= 0 && gy < Ww)
                                ? src[(size_t)gx * Ww + gy] : 0.f;
    }
    __syncthreads();

    // ---- Phase B: y-conv, in-place.  72 rows x 4 segs = 288 items. ----
    {
        int row = t >> 2;             // 0..71
        int c0  = (t & 3) * 16;       // 0,16,32,48
        float v[24];
#pragma unroll
        for (int i = 0; i < 24; i++) v[i] = s_in[row * SIN + c0 + i];
        __syncthreads();              // all windows loaded before overwrite
#pragma unroll
        for (int o = 0; o < 16; o++) {
            float s = 0.f;
#pragma unroll
            for (int k = 0; k < 9; k++) s += w[k] * v[o + k];
            s_in[row * SIN + c0 + o] = s;
        }
    }
    __syncthreads();

    // ---- Phase C: x-conv, register sliding window, fused min/max ----
    float lmin =  3.402823466e38f;
    float lmax = -3.402823466e38f;
    if (t < 256) {
        int col = t & 63;                 // 0..63
        int x0  = (t >> 6) * 16;          // 0,16,32,48
        float v[24];
#pragma unroll
        for (int i = 0; i < 24; i++) v[i] = s_in[(x0 + i) * SIN + col];

        float* dst = out + (size_t)z * HW + (size_t)(X0 + x0) * Ww + (Y0 + col);
#pragma unroll
        for (int o = 0; o < 16; o++) {
            float s = 0.f;
#pragma unroll
            for (int k = 0; k < 9; k++) s += w[k] * v[o + k];
            dst[(size_t)o * Ww] = s;
            lmin = fminf(lmin, s);
            lmax = fmaxf(lmax, s);
        }
    }

    // block reduce min/max (9 warps)
#pragma unroll
    for (int o = 16; o > 0; o >>= 1) {
        lmin = fminf(lmin, __shfl_xor_sync(0xFFFFFFFFu, lmin, o));
        lmax = fmaxf(lmax, __shfl_xor_sync(0xFFFFFFFFu, lmax, o));
    }
    if ((t & 31) == 0) { smin[t >> 5] = lmin; smax[t >> 5] = lmax; }
    __syncthreads();
    if (t < 16) {
        lmin = (t < 9) ? smin[t] :  3.402823466e38f;
        lmax = (t < 9) ? smax[t] : -3.402823466e38f;
#pragma unroll
        for (int o = 8; o > 0; o >>= 1) {
            lmin = fminf(lmin, __shfl_xor_sync(0x0000FFFFu, lmin, o));
            lmax = fmaxf(lmax, __shfl_xor_sync(0x0000FFFFu, lmax, o));
        }
        if (t == 0) {
            atomicMin(&g_minb, f2o(lmin));
            atomicMax(&g_maxb, f2o(lmax));
        }
    }
}

// ---------------------------------------------------------------------------
// Kernel 3: in-place min-max normalize of d_out, 2 float4 per thread.
// ---------------------------------------------------------------------------
__global__ void __launch_bounds__(256) k_norm(float4* __restrict__ out)
{
    int i = blockIdx.x * 512 + threadIdx.x;
    float mn = o2f(g_minb);
    float mx = o2f(g_maxb);
    float inv = 1.0f / (mx - mn);
    float4 a = out[i];
    float4 b = out[i + 256];
    a.x = (a.x - mn) * inv; a.y = (a.y - mn) * inv;
    a.z = (a.z - mn) * inv; a.w = (a.w - mn) * inv;
    b.x = (b.x - mn) * inv; b.y = (b.y - mn) * inv;
    b.z = (b.z - mn) * inv; b.w = (b.w - mn) * inv;
    out[i] = a;
    out[i + 256] = b;
}

// ---------------------------------------------------------------------------
// Launch: 4 z-chunks.  zconv chunks on the capture (legacy) stream; each
// records an event; a non-blocking side stream waits the event and runs the
// matching xyconv chunk -> zconv(i+1) overlaps xyconv(i) in the graph.
// Side stream joins back before k_norm.  Host-only handles, no device allocs.
// ---------------------------------------------------------------------------
extern "C" void kernel_launch(void* const* d_in, const int* in_sizes, int n_in,
                              void* d_out, int out_size)
{
    const float* inp  = (const float*)d_in[0];
    const float* mu_z = (const float*)d_in[1];
    const float* sigz = (const float*)d_in[2];
    const float* bxy  = (const float*)d_in[3];
    const float* bz   = (const float*)d_in[4];
    float* out = (float*)d_out;

    cudaStream_t s2;
    cudaStreamCreateWithFlags(&s2, cudaStreamNonBlocking);
    cudaEvent_t ez[4], ex;
    for (int i = 0; i < 4; i++)
        cudaEventCreateWithFlags(&ez[i], cudaEventDisableTiming);
    cudaEventCreateWithFlags(&ex, cudaEventDisableTiming);

    dim3 gz(HW4 / 128);               // 512 blocks per chunk
    dim3 gx(Ww / 64, Hh / 64, 8);     // (8, 8, 8) per chunk

    for (int i = 0; i < 4; i++) {
        k_zconv<<<gz, 128>>>((const float4*)inp, mu_z, sigz, bz, 8 * i);
        cudaEventRecord(ez[i], 0);
        cudaStreamWaitEvent(s2, ez[i], 0);
        k_xyconv<<<gx, 288, 0, s2>>>(bxy, out, 8 * i);
    }

    cudaEventRecord(ex, s2);
    cudaStreamWaitEvent(0, ex, 0);

    int n4 = OD * HW4;                // 2,097,152 float4s
    k_norm<<<n4 / 512, 256>>>((float4*)out);
}

// round 7
// speedup vs baseline: 1.4096x; 1.4096x over previous
#include <cuda_runtime.h>
#include <math.h>
#include <stdint.h>

#define Dd 128
#define Hh 512
#define Ww 512
#define OD 32
#define HW (Hh*Ww)
#define HW4 (HW/4)
#define INV_SQRT_2PI 0.3989422804014327f

// scratch: z-conv output (32,512,512) f32 = 33.5 MB
__device__ __align__(16) float g_tmp1[(size_t)OD * HW];
__device__ unsigned g_minb;
__device__ unsigned g_maxb;

__device__ __forceinline__ unsigned f2o(float f) {
    unsigned u = __float_as_uint(f);
    return (u & 0x80000000u) ? ~u : (u | 0x80000000u);
}
__device__ __forceinline__ float o2f(unsigned u) {
    return (u & 0x80000000u) ? __uint_as_float(u ^ 0x80000000u)
                             : __uint_as_float(~u);
}

// ---------------------------------------------------------------------------
// Kernel 1: strided z-conv, rolling-accumulator single sweep (R5 shape).
// 16 outputs/thread, 69 planes streamed once, 8-stage cp.async ring.
// Input reads: L2::evict_first (read-once stream, don't pollute L2).
// Scratch writes: L2::evict_last (keep resident for k_xyconv).
// ---------------------------------------------------------------------------
__global__ void __launch_bounds__(128) k_zconv(
    const float4* __restrict__ in,
    const float* __restrict__ p_mu, const float* __restrict__ p_sig,
    const float* __restrict__ p_bz)
{
    __shared__ float4 sb[8][128];

    int t = threadIdx.x;
    if (blockIdx.x == 0 && blockIdx.y == 0 && t == 0) {
        g_minb = 0xFFFFFFFFu;
        g_maxb = 0u;
    }

    int idx = blockIdx.x * 128 + t;             // 0 .. HW4-1
    int zo0 = blockIdx.y * 16;                  // first output z (0 or 16)
    int zstart = 4 * zo0 - 3;                   // input z at iz=0
    const float4* p0 = in + idx;
    unsigned sbase = (unsigned)__cvta_generic_to_shared(&sb[0][0]);

    uint64_t pol_f, pol_l;
    asm("createpolicy.fractional.L2::evict_first.b64 %0, 1.0;" : "=l"(pol_f));
    asm("createpolicy.fractional.L2::evict_last.b64 %0, 1.0;"  : "=l"(pol_l));

    float bz  = *p_bz;
    float z0  = expf(*p_mu + 0.5f * (*p_sig) * (*p_sig));
    float amp = INV_SQRT_2PI * z0;
    float inv2b2 = 1.0f / (2.0f * bz * bz);

    float wz[9];
#pragma unroll
    for (int k = 0; k < 9; k++) {
        float d = (float)(k - 4);
        wz[k] = expf(-d * d * inv2b2) * amp;
    }

    float4 acc[3];
#pragma unroll
    for (int j = 0; j < 3; j++) acc[j] = make_float4(0.f, 0.f, 0.f, 0.f);

#define ISSUE(P) do {                                                         \
        int z_ = zstart + (P);                                                \
        int ok_ = ((unsigned)z_ < 128u) ? 16 : 0;                             \
        int zc_ = z_ < 0 ? 0 : (z_ > 127 ? 127 : z_);                         \
        unsigned sa_ = sbase + ((((P) & 7) * 128 + t) * 16u);                 \
        asm volatile(                                                         \
            "cp.async.cg.shared.global.L2::cache_hint [%0], [%1], 16, %2, %3;"\
            :: "r"(sa_), "l"(p0 + (size_t)zc_ * HW4), "r"(ok_), "l"(pol_f)    \
            : "memory");                                                      \
        asm volatile("cp.async.commit_group;" ::: "memory");                  \
    } while (0)
#define WG(n) asm volatile("cp.async.wait_group " #n ";" ::: "memory")

    ISSUE(0); ISSUE(1); ISSUE(2); ISSUE(3); ISSUE(4); ISSUE(5); ISSUE(6);

    float4* outp = reinterpret_cast<float4*>(g_tmp1) + idx;

#pragma unroll
    for (int iz = 0; iz < 69; iz++) {
        if (iz + 7 < 69)      { ISSUE(iz + 7); WG(7); }
        else if (iz == 62)    WG(6);
        else if (iz == 63)    WG(5);
        else if (iz == 64)    WG(4);
        else if (iz == 65)    WG(3);
        else if (iz == 66)    WG(2);
        else if (iz == 67)    WG(1);
        else                  WG(0);

        float4 v = sb[iz & 7][t];
        int c = iz >> 2, q = iz & 3;            // compile-time (full unroll)

        if (q == 0 && c >= 2 && c <= 17) {      // kz=8 tap, retire j=c-2
            int j = c - 2;
            int s = j % 3;
            float w = wz[8];
            acc[s].x += w * v.x; acc[s].y += w * v.y;
            acc[s].z += w * v.z; acc[s].w += w * v.w;
            float4* dp = outp + (size_t)(zo0 + j) * HW4;
            asm volatile(
                "st.global.L2::cache_hint.v4.f32 [%0], {%1,%2,%3,%4}, %5;"
                :: "l"(dp), "f"(acc[s].x), "f"(acc[s].y),
                   "f"(acc[s].z), "f"(acc[s].w), "l"(pol_l) : "memory");
            acc[s] = make_float4(0.f, 0.f, 0.f, 0.f);
        }
        if (c >= 1 && c <= 16) {                // kz=4+q tap for j=c-1
            int s = (c - 1) % 3;
            float w = wz[4 + q];
            acc[s].x += w * v.x; acc[s].y += w * v.y;
            acc[s].z += w * v.z; acc[s].w += w * v.w;
        }
        if (c <= 15) {                          // kz=q tap for j=c
            int s = c % 3;
            float w = wz[q];
            acc[s].x += w * v.x; acc[s].y += w * v.y;
            acc[s].z += w * v.z; acc[s].w += w * v.w;
        }
    }
#undef ISSUE
#undef WG
}

// ---------------------------------------------------------------------------
// Kernel 2: fused x-conv + y-conv, 64x64 tile (72x72 halo), single in-place
// smem buffer, stride 76 (16B-aligned rows -> float4 LDS, conflict-free with
// the row = t%72 mapping), register sliding windows, fused global min/max.
// ---------------------------------------------------------------------------
#define SIN 76
__global__ void __launch_bounds__(288) k_xyconv(
    const float* __restrict__ p_bxy, float* __restrict__ out)
{
    __shared__ __align__(16) float s_in[72 * SIN];
    __shared__ float smin[16], smax[16];

    int z  = blockIdx.z;
    int X0 = blockIdx.y * 64;
    int Y0 = blockIdx.x * 64;
    int t  = threadIdx.x;

    float bxy = *p_bxy;
    float inv2b2 = 1.0f / (2.0f * bxy * bxy);
    float w[9];
#pragma unroll
    for (int k = 0; k < 9; k++) {
        float d = (float)(k - 4);
        w[k] = expf(-d * d * inv2b2);
    }

    const float* src = g_tmp1 + (size_t)z * HW;

    // ---- Phase A: load 72x72 halo (zero padded), coalesced ----
#pragma unroll
    for (int it = 0; it < 18; it++) {            // 72*72 / 288 = 18
        int i = it * 288 + t;
        int r = i / 72, c = i % 72;
        int gx = X0 - 4 + r, gy = Y0 - 4 + c;
        s_in[r * SIN + c] = (gx >= 0 && gx < Hh && gy >= 0 && gy < Ww)
                                ? src[(size_t)gx * Ww + gy] : 0.f;
    }
    __syncthreads();

    // ---- Phase B: y-conv, in-place, float4 LDS (conflict-free) ----
    {
        int row = t % 72;             // lanes 0..31 -> consecutive rows
        int c0  = (t / 72) * 16;      // 0,16,32,48
        float v[24];
        float4* vp = reinterpret_cast<float4*>(v);
#pragma unroll
        for (int j = 0; j < 6; j++)
            vp[j] = *reinterpret_cast<float4*>(&s_in[row * SIN + c0 + 4 * j]);
        __syncthreads();              // all windows loaded before overwrite
        float r_[16];
#pragma unroll
        for (int o = 0; o < 16; o++) {
            float s = 0.f;
#pragma unroll
            for (int k = 0; k < 9; k++) s += w[k] * v[o + k];
            r_[o] = s;
        }
#pragma unroll
        for (int g = 0; g < 4; g++)
            *reinterpret_cast<float4*>(&s_in[row * SIN + c0 + 4 * g]) =
                make_float4(r_[4*g], r_[4*g+1], r_[4*g+2], r_[4*g+3]);
    }
    __syncthreads();

    // ---- Phase C: x-conv, register sliding window, fused min/max ----
    float lmin =  3.402823466e38f;
    float lmax = -3.402823466e38f;
    if (t < 256) {
        int col = t & 63;                 // 0..63
        int x0  = (t >> 6) * 16;          // 0,16,32,48
        float v[24];
#pragma unroll
        for (int i = 0; i < 24; i++) v[i] = s_in[(x0 + i) * SIN + col];

        float* dst = out + (size_t)z * HW + (size_t)(X0 + x0) * Ww + (Y0 + col);
#pragma unroll
        for (int o = 0; o < 16; o++) {
            float s = 0.f;
#pragma unroll
            for (int k = 0; k < 9; k++) s += w[k] * v[o + k];
            dst[(size_t)o * Ww] = s;
            lmin = fminf(lmin, s);
            lmax = fmaxf(lmax, s);
        }
    }

    // block reduce min/max (9 warps)
#pragma unroll
    for (int o = 16; o > 0; o >>= 1) {
        lmin = fminf(lmin, __shfl_xor_sync(0xFFFFFFFFu, lmin, o));
        lmax = fmaxf(lmax, __shfl_xor_sync(0xFFFFFFFFu, lmax, o));
    }
    if ((t & 31) == 0) { smin[t >> 5] = lmin; smax[t >> 5] = lmax; }
    __syncthreads();
    if (t < 16) {
        lmin = (t < 9) ? smin[t] :  3.402823466e38f;
        lmax = (t < 9) ? smax[t] : -3.402823466e38f;
#pragma unroll
        for (int o = 8; o > 0; o >>= 1) {
            lmin = fminf(lmin, __shfl_xor_sync(0x0000FFFFu, lmin, o));
            lmax = fmaxf(lmax, __shfl_xor_sync(0x0000FFFFu, lmax, o));
        }
        if (t == 0) {
            atomicMin(&g_minb, f2o(lmin));
            atomicMax(&g_maxb, f2o(lmax));
        }
    }
}

// ---------------------------------------------------------------------------
// Kernel 3: in-place min-max normalize of d_out, 2 float4 per thread.
// ---------------------------------------------------------------------------
__global__ void __launch_bounds__(256) k_norm(float4* __restrict__ out)
{
    int i = blockIdx.x * 512 + threadIdx.x;
    float mn = o2f(g_minb);
    float mx = o2f(g_maxb);
    float inv = 1.0f / (mx - mn);
    float4 a = out[i];
    float4 b = out[i + 256];
    a.x = (a.x - mn) * inv; a.y = (a.y - mn) * inv;
    a.z = (a.z - mn) * inv; a.w = (a.w - mn) * inv;
    b.x = (b.x - mn) * inv; b.y = (b.y - mn) * inv;
    b.z = (b.z - mn) * inv; b.w = (b.w - mn) * inv;
    out[i] = a;
    out[i + 256] = b;
}

extern "C" void kernel_launch(void* const* d_in, const int* in_sizes, int n_in,
                              void* d_out, int out_size)
{
    const float* inp  = (const float*)d_in[0];
    const float* mu_z = (const float*)d_in[1];
    const float* sigz = (const float*)d_in[2];
    const float* bxy  = (const float*)d_in[3];
    const float* bz   = (const float*)d_in[4];
    float* out = (float*)d_out;

    dim3 g1(HW4 / 128, 2);            // (512, 2) = 1024 blocks, 128 thr
    k_zconv<<<g1, 128>>>((const float4*)inp, mu_z, sigz, bz);

    dim3 g2(Ww / 64, Hh / 64, OD);    // (8, 8, 32) = 2048 blocks
    k_xyconv<<<g2, 288>>>(bxy, out);

    int n4 = OD * HW4;                // 2,097,152 float4s
    k_norm<<<n4 / 512, 256>>>((float4*)out);
}